// round 16
// baseline (speedup 1.0000x reference)
#include <cuda_runtime.h>
#include <cuda_fp16.h>
#include <cstdint>
#include <math.h>

#define S_LEN 4096
#define B_SZ  2
#define HD    128
#define DM    4096
#define NROWS (B_SZ * S_LEN)
#define NEGINF (-1e30f)
#define NSPLIT 4

// scratch
__device__ uint32_t g_qh[NROWS * HD / 2];     // [row][d-pair] f16x2, SCALE folded
__device__ uint32_t g_kh[NROWS * HD / 2];     // [row][d-pair] f16x2
__device__ uint32_t g_vt[HD * NROWS / 2];     // [d][global-row-pair] f16x2
__device__ uint32_t g_wt[3 * HD * DM / 2];    // W f16x2 plain [n][k-pair]
__device__ float    g_part[6 * NROWS * HD];   // qkv K-split partials
__device__ float g_opart[NSPLIT * NROWS * HD];
__device__ float g_mpart[NSPLIT * NROWS];
__device__ float g_lpart[NSPLIT * NROWS];

// ---------------- helpers ----------------
__device__ __forceinline__ uint32_t h2(float lo, float hi) {
    uint32_t r;
    asm("cvt.rn.f16x2.f32 %0, %1, %2;" : "=r"(r) : "f"(hi), "f"(lo));
    return r;
}
__device__ __forceinline__ void mma16(float c[4], const uint32_t a[4], const uint32_t b[2]) {
    asm volatile(
        "mma.sync.aligned.m16n8k16.row.col.f32.f16.f16.f32 "
        "{%0,%1,%2,%3}, {%4,%5,%6,%7}, {%8,%9}, {%0,%1,%2,%3};"
        : "+f"(c[0]), "+f"(c[1]), "+f"(c[2]), "+f"(c[3])
        : "r"(a[0]), "r"(a[1]), "r"(a[2]), "r"(a[3]), "r"(b[0]), "r"(b[1]));
}
__device__ __forceinline__ void ldmx4(uint32_t r[4], uint32_t saddr) {
    asm volatile("ldmatrix.sync.aligned.m8n8.x4.shared.b16 {%0,%1,%2,%3}, [%4];"
                 : "=r"(r[0]), "=r"(r[1]), "=r"(r[2]), "=r"(r[3]) : "r"(saddr));
}
__device__ __forceinline__ uint32_t smem_u32(const void* p) {
    uint32_t a;
    asm("{ .reg .u64 t; cvta.to.shared.u64 t, %1; cvt.u32.u64 %0, t; }" : "=r"(a) : "l"(p));
    return a;
}
#define CP_ASYNC16(dst_u32, src_ptr) \
    asm volatile("cp.async.cg.shared.global [%0], [%1], 16;" \
                 :: "r"(dst_u32), "l"(src_ptr) : "memory")
#define CP_COMMIT()  asm volatile("cp.async.commit_group;" ::: "memory")
#define CP_WAIT(n)   asm volatile("cp.async.wait_group %0;" :: "n"(n) : "memory")

// ===========================================================================
// Kernel A0: W -> fp16 packed [n][k-pair] (plain)
// ===========================================================================
__global__ __launch_bounds__(256) void wconv_kernel(
    const float* __restrict__ Wq,
    const float* __restrict__ Wk,
    const float* __restrict__ Wv)
{
    const int f   = (blockIdx.x * 256 + threadIdx.x) * 4;
    const int per = HD * DM;
    const int z   = f / per;
    const float* src = ((z == 0) ? Wq : (z == 1) ? Wk : Wv);
    const float4 v = *(const float4*)(src + (f - z * per));
    *(uint2*)(g_wt + f / 2) = make_uint2(h2(v.x, v.y), h2(v.z, v.w));
}

// ===========================================================================
// Kernel A: QKV projection, fp16 mma, K-split x2 -> fp32 partials.
// B fragments via ldmatrix.x4 from plain [n][k-pair] smem (stride 20 words).
// ===========================================================================
#define PJW 40
#define WJW 20
#define STG 3
#define XSTAGE (128 * PJW)
#define WSTAGE (128 * WJW)
#define PROJ_SMEM (STG * (XSTAGE + WSTAGE) * 4)

__global__ __launch_bounds__(256, 2) void qkv_mma_kernel(const float* __restrict__ x)
{
    extern __shared__ uint32_t smq[];
    uint32_t* Xs = smq;
    uint32_t* Ws = smq + STG * XSTAGE;

    const int t    = threadIdx.x;
    const int lane = t & 31;
    const int w    = t >> 5;
    const int g    = lane >> 2;
    const int tg   = lane & 3;
    const int wm   = w & 3;
    const int wn   = w >> 2;
    const int quad = lane >> 3;
    const int r8   = lane & 7;
    const int z    = blockIdx.y;
    const int ks   = blockIdx.z;
    const int m0   = blockIdx.x * 128;
    const int K0   = ks * (DM / 2);
    const int K0w  = ks * (DM / 4);
    const uint32_t* __restrict__ wt = g_wt + (size_t)z * (HD * DM / 2);

    int rowL[4], segL[4];
    uint32_t sbyX[4];
#pragma unroll
    for (int i = 0; i < 4; i++) {
        int idx = i * 256 + t;
        rowL[i] = idx >> 3;
        segL[i] = idx & 7;
        sbyX[i] = (uint32_t)(rowL[i] * PJW + segL[i] * 4) * 4;
    }
    int wrowL[2], wsegL[2];
    uint32_t sbyW[2];
#pragma unroll
    for (int i = 0; i < 2; i++) {
        int idx = i * 256 + t;
        wrowL[i] = idx >> 2;
        wsegL[i] = idx & 3;
        sbyW[i]  = (uint32_t)(wrowL[i] * WJW + wsegL[i] * 4) * 4;
    }
    const uint32_t sxs = smem_u32(Xs);
    const uint32_t sws = smem_u32(Ws);

    float acc[16][4];
#pragma unroll
    for (int n = 0; n < 16; n++)
#pragma unroll
        for (int j = 0; j < 4; j++) acc[n][j] = 0.f;

    const uint32_t am0 = (wm * 32 + g) * PJW;
    const uint32_t am1 = (wm * 32 + 16 + g) * PJW;
    // ldmatrix B lane base: row = wn*64 + (quad>>1)*8 + r8, word col = (quad&1)*4
    const uint32_t wlmOff = ((wn * 64 + (quad >> 1) * 8 + r8) * WJW + (quad & 1) * 4) * 4;

#define ISSUE(c, s) do { \
    const uint32_t _xd = sxs + (s) * (XSTAGE * 4); \
    const uint32_t _wd = sws + (s) * (WSTAGE * 4); \
    _Pragma("unroll") \
    for (int _i = 0; _i < 4; _i++) \
        CP_ASYNC16(_xd + sbyX[_i], x + (size_t)(m0 + rowL[_i]) * DM + K0 + (c) * 32 + segL[_i] * 4); \
    _Pragma("unroll") \
    for (int _i = 0; _i < 2; _i++) \
        CP_ASYNC16(_wd + sbyW[_i], wt + (size_t)wrowL[_i] * (DM / 2) + K0w + (c) * 16 + wsegL[_i] * 4); \
    CP_COMMIT(); \
} while (0)

    ISSUE(0, 0);
    ISSUE(1, 1);

    const int NCH = DM / 64;
    for (int c = 0; c < NCH; c++) {
        if (c == NCH - 1) { CP_WAIT(0); } else { CP_WAIT(1); }
        __syncthreads();
        if (c + 2 < NCH) ISSUE(c + 2, (c + 2) % STG);

        const float*   Xf = (const float*)(Xs + (c % STG) * XSTAGE);
        const uint32_t wSt = sws + (c % STG) * (WSTAGE * 4) + wlmOff;
#pragma unroll
        for (int s = 0; s < 2; s++) {
            const int kb = s * 16 + 2 * tg;
            float2 p00 = *(const float2*)&Xf[am0 + kb];
            float2 p01 = *(const float2*)&Xf[am0 + kb + 8];
            float2 p02 = *(const float2*)&Xf[am0 + 8 * PJW + kb];
            float2 p03 = *(const float2*)&Xf[am0 + 8 * PJW + kb + 8];
            uint32_t a0[4] = { h2(p00.x, p00.y), h2(p02.x, p02.y),
                               h2(p01.x, p01.y), h2(p03.x, p03.y) };
            float2 p10 = *(const float2*)&Xf[am1 + kb];
            float2 p11 = *(const float2*)&Xf[am1 + kb + 8];
            float2 p12 = *(const float2*)&Xf[am1 + 8 * PJW + kb];
            float2 p13 = *(const float2*)&Xf[am1 + 8 * PJW + kb + 8];
            uint32_t a1[4] = { h2(p10.x, p10.y), h2(p12.x, p12.y),
                               h2(p11.x, p11.y), h2(p13.x, p13.y) };
#pragma unroll
            for (int p = 0; p < 4; p++) {
                uint32_t bm[4];
                ldmx4(bm, wSt + (p * 16 * WJW + s * 8) * 4);
                mma16(acc[2 * p],         a0, bm);
                mma16(acc[8 + 2 * p],     a1, bm);
                mma16(acc[2 * p + 1],     a0, bm + 2);
                mma16(acc[8 + 2 * p + 1], a1, bm + 2);
            }
        }
    }
#undef ISSUE

    float* dp = g_part + (size_t)(z * 2 + ks) * NROWS * HD;
#pragma unroll
    for (int mf = 0; mf < 2; mf++) {
        const int r0 = m0 + wm * 32 + mf * 16 + g;
        const int r1 = r0 + 8;
#pragma unroll
        for (int n8 = 0; n8 < 8; n8++) {
            const float* a = acc[mf * 8 + n8];
            const int c = wn * 64 + n8 * 8 + 2 * tg;
            *(float2*)(dp + (size_t)r0 * HD + c) = make_float2(a[0], a[1]);
            *(float2*)(dp + (size_t)r1 * HD + c) = make_float2(a[2], a[3]);
        }
    }
}

// ===========================================================================
// Kernel A2: reduce K-split partials; RoPE + fp16 pack; V transpose (unchanged)
// ===========================================================================
__global__ __launch_bounds__(256) void qkv_reduce()
{
    __shared__ uint32_t st[128 * 68];

    const int t    = threadIdx.x;
    const int z    = blockIdx.y;
    const int rblk = blockIdx.x * 128;
    const int rl   = t >> 1;
    const int hf   = t & 1;
    const int row  = rblk + rl;

    const float* p0 = g_part + (size_t)(2 * z)     * NROWS * HD + (size_t)row * HD;
    const float* p1 = g_part + (size_t)(2 * z + 1) * NROWS * HD + (size_t)row * HD;

    if (z < 2) {
        const float fs   = (z == 0) ? 0.08838834764831845f : 1.0f;
        const float srow = (float)(row & (S_LEN - 1));
#pragma unroll
        for (int i = 0; i < 32; i++) {
            const int p = hf * 32 + i;
            const float2 a0 = *(const float2*)(p0 + 2 * p);
            const float2 a1 = *(const float2*)(p1 + 2 * p);
            const float v0 = a0.x + a1.x;
            const float v1 = a0.y + a1.y;
            const float th = exp2f(-0.4152410118609203f * (float)p);
            float sn, cs;
            sincosf(srow * th, &sn, &cs);
            st[rl * 68 + p] = h2((v0 * cs - v1 * sn) * fs, (v1 * cs + v0 * sn) * fs);
        }
        __syncthreads();
        uint32_t* dsth = (z == 0) ? g_qh : g_kh;
#pragma unroll
        for (int j = 0; j < 32; j++) {
            const int idx = j * 256 + t;
            const int rr = idx >> 6, cc = idx & 63;
            dsth[(size_t)(rblk + rr) * 64 + cc] = st[rr * 68 + cc];
        }
    } else {
        __half* vh = (__half*)st;
#pragma unroll
        for (int i = 0; i < 32; i++) {
            const int p = hf * 32 + i;
            const float2 a0 = *(const float2*)(p0 + 2 * p);
            const float2 a1 = *(const float2*)(p1 + 2 * p);
            vh[(2 * p)     * 132 + rl] = __float2half(a0.x + a1.x);
            vh[(2 * p + 1) * 132 + rl] = __float2half(a0.y + a1.y);
        }
        __syncthreads();
#pragma unroll
        for (int j = 0; j < 32; j++) {
            const int idx = j * 256 + t;
            const int d = idx >> 6, rp = idx & 63;
            g_vt[(size_t)d * (NROWS / 2) + (rblk >> 1) + rp] =
                *(const uint32_t*)&vh[d * 132 + rp * 2];
        }
    }
}

// ===========================================================================
// Kernel B: causal flash attention, fp16 mma, BM=64, 128 threads, ldmatrix
// fragment loads for K, V, P. cp.async K/V double buffer, NSPLIT KV split.
// ===========================================================================
#define KSTGW (64 * 68)
#define VSTGW (128 * 36)
#define STGW  (KSTGW + VSTGW)
#define PP_STR 36
#define ATT_SMEM ((2 * STGW + 4 * 16 * PP_STR) * 4)   // 80896 B

__global__ __launch_bounds__(128, 2) void attn_kernel()
{
    extern __shared__ uint32_t sma[];
    uint32_t* Ps = sma + 2 * STGW;

    const int t    = threadIdx.x;
    const int lane = t & 31;
    const int w    = t >> 5;
    const int g    = lane >> 2;
    const int tg   = lane & 3;
    const int quad = lane >> 3;
    const int r8   = lane & 7;
    const int b    = blockIdx.y;
    const int h    = blockIdx.z;
    const int qt   = (S_LEN / 64 - 1) - blockIdx.x;

    const int gr0 = qt * 64 + w * 16 + g;
    const int gr1 = gr0 + 8;
    const int statbase = h * NROWS + b * S_LEN;

    const int ntiles = qt + 1;
    const int cs = (ntiles + NSPLIT - 1) / NSPLIT;
    const int j0 = h * cs;
    const int j1 = min(ntiles, j0 + cs);
    if (j0 >= j1) {
        if (tg == 0) {
            g_mpart[statbase + gr0] = NEGINF; g_lpart[statbase + gr0] = 0.f;
            g_mpart[statbase + gr1] = NEGINF; g_lpart[statbase + gr1] = 0.f;
        }
        return;
    }

    int kkey[8], kseg[8], vd[8], vseg[8];
#pragma unroll
    for (int i = 0; i < 8; i++) {
        int idx = i * 128 + t;
        kkey[i] = idx >> 4; kseg[i] = idx & 15;
        vd[i]   = idx >> 3; vseg[i] = idx & 7;
    }
    const uint32_t sbase = smem_u32(sma);
    // ldmatrix lane bases (byte offsets)
    const uint32_t klm = (((quad >> 1) * 8 + r8) * 68 + (quad & 1) * 4) * 4;      // B frags (K)
    const uint32_t vlm = (((quad >> 1) * 8 + r8) * 36 + (quad & 1) * 4) * 4;      // B frags (V)
    const uint32_t plm = (((quad & 1) * 8 + r8) * PP_STR + (quad >> 1) * 4) * 4;  // A frags (P)
    const uint32_t pwAddr = sbase + (2 * STGW + w * 16 * PP_STR) * 4 + plm;

#define AISSUE(jt, s) do { \
    const size_t _brow = (size_t)b * S_LEN + (size_t)(jt) * 64; \
    const uint32_t _kd = sbase + (s) * (STGW * 4); \
    const uint32_t _vd = _kd + KSTGW * 4; \
    _Pragma("unroll") \
    for (int _i = 0; _i < 8; _i++) { \
        CP_ASYNC16(_kd + kkey[_i] * 272 + kseg[_i] * 16, \
                   g_kh + (_brow + kkey[_i]) * 64 + kseg[_i] * 4); \
        CP_ASYNC16(_vd + vd[_i] * 144 + vseg[_i] * 16, \
                   g_vt + (size_t)vd[_i] * (NROWS / 2) + (_brow >> 1) + vseg[_i] * 4); \
    } \
    CP_COMMIT(); \
} while (0)

    const uint32_t* qw = g_qh + (size_t)b * S_LEN * 64;
    uint32_t qf[8][4];
#pragma unroll
    for (int s = 0; s < 8; s++) {
        qf[s][0] = qw[(size_t)gr0 * 64 + s * 8 + tg];
        qf[s][1] = qw[(size_t)gr1 * 64 + s * 8 + tg];
        qf[s][2] = qw[(size_t)gr0 * 64 + s * 8 + tg + 4];
        qf[s][3] = qw[(size_t)gr1 * 64 + s * 8 + tg + 4];
    }

    float of[16][4];
#pragma unroll
    for (int n = 0; n < 16; n++)
#pragma unroll
        for (int j = 0; j < 4; j++) of[n][j] = 0.f;
    float m0 = NEGINF, m1 = NEGINF, l0 = 0.f, l1 = 0.f;

    uint32_t* pw = &Ps[w * 16 * PP_STR];

    AISSUE(j0, 0);

    for (int jt = j0; jt < j1; jt++) {
        const int buf = (jt - j0) & 1;
        CP_WAIT(0);
        __syncthreads();
        if (jt + 1 < j1) AISSUE(jt + 1, buf ^ 1);

        const uint32_t kAddr = sbase + buf * (STGW * 4) + klm;
        const uint32_t vAddr = sbase + buf * (STGW * 4) + KSTGW * 4 + vlm;

        // S = Q K^T  (K B-frags via ldmatrix)
        float sf[8][4];
#pragma unroll
        for (int n = 0; n < 8; n++)
#pragma unroll
            for (int j = 0; j < 4; j++) sf[n][j] = 0.f;
#pragma unroll
        for (int s = 0; s < 8; s++) {
#pragma unroll
            for (int p = 0; p < 4; p++) {
                uint32_t bm[4];
                ldmx4(bm, kAddr + (p * 16 * 68 + s * 8) * 4);
                mma16(sf[2 * p],     qf[s], bm);
                mma16(sf[2 * p + 1], qf[s], bm + 2);
            }
        }

        // causal mask: only the diagonal tile straddles
        if (jt == qt) {
#pragma unroll
            for (int n8 = 0; n8 < 8; n8++) {
                const int c0 = jt * 64 + n8 * 8 + 2 * tg;
                const int c1 = c0 + 1;
                if (c0 > gr0) sf[n8][0] = NEGINF;
                if (c1 > gr0) sf[n8][1] = NEGINF;
                if (c0 > gr1) sf[n8][2] = NEGINF;
                if (c1 > gr1) sf[n8][3] = NEGINF;
            }
        }

        float mx0 = NEGINF, mx1 = NEGINF;
#pragma unroll
        for (int n8 = 0; n8 < 8; n8++) {
            mx0 = fmaxf(mx0, fmaxf(sf[n8][0], sf[n8][1]));
            mx1 = fmaxf(mx1, fmaxf(sf[n8][2], sf[n8][3]));
        }
        mx0 = fmaxf(mx0, __shfl_xor_sync(0xFFFFFFFFu, mx0, 1));
        mx0 = fmaxf(mx0, __shfl_xor_sync(0xFFFFFFFFu, mx0, 2));
        mx1 = fmaxf(mx1, __shfl_xor_sync(0xFFFFFFFFu, mx1, 1));
        mx1 = fmaxf(mx1, __shfl_xor_sync(0xFFFFFFFFu, mx1, 2));

        const float mn0 = fmaxf(m0, mx0);
        const float mn1 = fmaxf(m1, mx1);
        const float al0 = __expf(m0 - mn0);
        const float al1 = __expf(m1 - mn1);

        float sum0 = 0.f, sum1 = 0.f;
#pragma unroll
        for (int n8 = 0; n8 < 8; n8++) {
            sf[n8][0] = __expf(sf[n8][0] - mn0);
            sf[n8][1] = __expf(sf[n8][1] - mn0);
            sf[n8][2] = __expf(sf[n8][2] - mn1);
            sf[n8][3] = __expf(sf[n8][3] - mn1);
            sum0 += sf[n8][0] + sf[n8][1];
            sum1 += sf[n8][2] + sf[n8][3];
        }
        sum0 += __shfl_xor_sync(0xFFFFFFFFu, sum0, 1);
        sum0 += __shfl_xor_sync(0xFFFFFFFFu, sum0, 2);
        sum1 += __shfl_xor_sync(0xFFFFFFFFu, sum1, 1);
        sum1 += __shfl_xor_sync(0xFFFFFFFFu, sum1, 2);
        l0 = l0 * al0 + sum0; m0 = mn0;
        l1 = l1 * al1 + sum1; m1 = mn1;

        // stage P as f16x2 key-pairs
#pragma unroll
        for (int n8 = 0; n8 < 8; n8++) {
            pw[g * PP_STR + n8 * 4 + tg]       = h2(sf[n8][0], sf[n8][1]);
            pw[(g + 8) * PP_STR + n8 * 4 + tg] = h2(sf[n8][2], sf[n8][3]);
        }
        __syncwarp();

#pragma unroll
        for (int n8 = 0; n8 < 16; n8++) {
            of[n8][0] *= al0; of[n8][1] *= al0;
            of[n8][2] *= al1; of[n8][3] *= al1;
        }

        // O += P V  (P A-frags and V B-frags via ldmatrix)
#pragma unroll
        for (int s = 0; s < 4; s++) {
            uint32_t af[4];
            ldmx4(af, pwAddr + s * 32);
#pragma unroll
            for (int p = 0; p < 8; p++) {
                uint32_t bm[4];
                ldmx4(bm, vAddr + (p * 16 * 36 + s * 8) * 4);
                mma16(of[2 * p],     af, bm);
                mma16(of[2 * p + 1], af, bm + 2);
            }
        }
    }
#undef AISSUE

    const float inv0 = (l0 > 0.f) ? 1.0f / l0 : 0.f;
    const float inv1 = (l1 > 0.f) ? 1.0f / l1 : 0.f;
    float* ob = g_opart + ((size_t)h * NROWS + (size_t)b * S_LEN) * HD;
#pragma unroll
    for (int n8 = 0; n8 < 16; n8++) {
        const int c = n8 * 8 + 2 * tg;
        *(float2*)(ob + (size_t)gr0 * HD + c) = make_float2(of[n8][0] * inv0, of[n8][1] * inv0);
        *(float2*)(ob + (size_t)gr1 * HD + c) = make_float2(of[n8][2] * inv1, of[n8][3] * inv1);
    }
    if (tg == 0) {
        g_mpart[statbase + gr0] = m0; g_lpart[statbase + gr0] = l0;
        g_mpart[statbase + gr1] = m1; g_lpart[statbase + gr1] = l1;
    }
}

// ===========================================================================
// Kernel C: combine the NSPLIT partial-softmax results (unchanged)
// ===========================================================================
__global__ __launch_bounds__(256) void combine_kernel(float* __restrict__ out)
{
    const int idx = blockIdx.x * 256 + threadIdx.x;
    const int row = idx >> 5;
    const int c4  = idx & 31;

    float mh[NSPLIT], lh[NSPLIT];
    float M = NEGINF;
#pragma unroll
    for (int h = 0; h < NSPLIT; h++) {
        mh[h] = g_mpart[h * NROWS + row];
        lh[h] = g_lpart[h * NROWS + row];
        M = fmaxf(M, mh[h]);
    }
    float wsum = 0.f, wh[NSPLIT];
#pragma unroll
    for (int h = 0; h < NSPLIT; h++) {
        wh[h] = lh[h] * __expf(mh[h] - M);
        wsum += wh[h];
    }
    const float inv = 1.0f / wsum;

    const size_t off = ((size_t)row << 7) + (c4 << 2);
    float4 r = make_float4(0.f, 0.f, 0.f, 0.f);
#pragma unroll
    for (int h = 0; h < NSPLIT; h++) {
        const float wn = wh[h] * inv;
        if (wn > 0.f) {
            const float4 a = *(const float4*)(g_opart + (size_t)h * NROWS * HD + off);
            r.x += wn * a.x; r.y += wn * a.y; r.z += wn * a.z; r.w += wn * a.w;
        }
    }
    *(float4*)(out + off) = r;
}

// ===========================================================================
extern "C" void kernel_launch(void* const* d_in, const int* in_sizes, int n_in,
                              void* d_out, int out_size)
{
    const float* x  = (const float*)d_in[0];
    const float* Wq = (const float*)d_in[1];
    const float* Wk = (const float*)d_in[2];
    const float* Wv = (const float*)d_in[3];
    float* out = (float*)d_out;

    cudaFuncSetAttribute(qkv_mma_kernel, cudaFuncAttributeMaxDynamicSharedMemorySize, PROJ_SMEM);
    cudaFuncSetAttribute(attn_kernel,    cudaFuncAttributeMaxDynamicSharedMemorySize, ATT_SMEM);

    wconv_kernel<<<(3 * HD * DM / 4) / 256, 256>>>(Wq, Wk, Wv);
    qkv_mma_kernel<<<dim3(NROWS / 128, 3, 2), 256, PROJ_SMEM>>>(x);
    qkv_reduce<<<dim3(NROWS / 128, 3), 256>>>();
    attn_kernel<<<dim3(S_LEN / 64, B_SZ, NSPLIT), 128, ATT_SMEM>>>();
    combine_kernel<<<(NROWS * 32) / 256, 256>>>(out);
}